// round 1
// baseline (speedup 1.0000x reference)
#include <cuda_runtime.h>
#include <cuda_bf16.h>

// Problem shape (fixed by reference setup_inputs)
#define B_DIM 32
#define C_DIM 512
#define HW    4096            // 64*64
#define KTOP  256             // 0.5 * C
#define NBC   (B_DIM * C_DIM) // 16384

// Scratch (no cudaMalloc allowed)
__device__ float g_ssq[NBC];   // per-(b,c) sum of targets^2  (ranking key)
__device__ float g_ssd[NBC];   // per-(b,c) sum of (in - tgt)^2
__device__ float g_batch[B_DIM];

// ---------------------------------------------------------------------------
// Kernel 1: one block per (b,c). 256 threads, each reads 4x float4 from each
// tensor (16 floats), computes ssq(target) and ssd, block-reduces both.
// This is the only kernel that touches the 512 MB; keep it pure streaming.
// ---------------------------------------------------------------------------
__global__ __launch_bounds__(256) void bc_reduce_kernel(
    const float* __restrict__ inp,
    const float* __restrict__ tgt)
{
    const int bc = blockIdx.x;
    const float4* __restrict__ ip =
        reinterpret_cast<const float4*>(inp + (size_t)bc * HW);
    const float4* __restrict__ tp =
        reinterpret_cast<const float4*>(tgt + (size_t)bc * HW);

    const int t = threadIdx.x;

    float ssq = 0.0f;
    float ssd = 0.0f;

#pragma unroll
    for (int i = 0; i < 4; i++) {
        float4 a = ip[t + i * 256];
        float4 b = tp[t + i * 256];
        ssq = fmaf(b.x, b.x, ssq);
        ssq = fmaf(b.y, b.y, ssq);
        ssq = fmaf(b.z, b.z, ssq);
        ssq = fmaf(b.w, b.w, ssq);
        float dx = a.x - b.x;
        float dy = a.y - b.y;
        float dz = a.z - b.z;
        float dw = a.w - b.w;
        ssd = fmaf(dx, dx, ssd);
        ssd = fmaf(dy, dy, ssd);
        ssd = fmaf(dz, dz, ssd);
        ssd = fmaf(dw, dw, ssd);
    }

    // warp reduce
#pragma unroll
    for (int off = 16; off > 0; off >>= 1) {
        ssq += __shfl_xor_sync(0xFFFFFFFFu, ssq, off);
        ssd += __shfl_xor_sync(0xFFFFFFFFu, ssd, off);
    }

    __shared__ float s_ssq[8];
    __shared__ float s_ssd[8];
    const int warp = t >> 5;
    const int lane = t & 31;
    if (lane == 0) {
        s_ssq[warp] = ssq;
        s_ssd[warp] = ssd;
    }
    __syncthreads();

    if (warp == 0) {
        float q = (lane < 8) ? s_ssq[lane] : 0.0f;
        float d = (lane < 8) ? s_ssd[lane] : 0.0f;
#pragma unroll
        for (int off = 4; off > 0; off >>= 1) {
            q += __shfl_xor_sync(0xFFFFFFFFu, q, off);
            d += __shfl_xor_sync(0xFFFFFFFFu, d, off);
        }
        if (lane == 0) {
            g_ssq[bc] = q;
            g_ssd[bc] = d;
        }
    }
}

// ---------------------------------------------------------------------------
// Kernel 2: one block per batch element, 512 threads (one per channel).
// Top-k by rank counting: keep channel c iff #{j : ssq[j] > ssq[c]} < KTOP.
// (sqrt is monotone; rank on sum-of-squares directly.) Then block-reduce the
// kept ssd into g_batch[b]. 512^2 SMEM compares = trivial.
// ---------------------------------------------------------------------------
__global__ __launch_bounds__(512) void select_kernel()
{
    __shared__ float s_norm[C_DIM];
    __shared__ float s_part[16];

    const int b = blockIdx.x;
    const int c = threadIdx.x;

    const float v = g_ssq[b * C_DIM + c];
    s_norm[c] = v;
    __syncthreads();

    int cnt = 0;
#pragma unroll 8
    for (int j = 0; j < C_DIM; j++) {
        cnt += (s_norm[j] > v) ? 1 : 0;
    }

    float contrib = (cnt < KTOP) ? g_ssd[b * C_DIM + c] : 0.0f;

#pragma unroll
    for (int off = 16; off > 0; off >>= 1)
        contrib += __shfl_xor_sync(0xFFFFFFFFu, contrib, off);

    const int warp = c >> 5;
    const int lane = c & 31;
    if (lane == 0) s_part[warp] = contrib;
    __syncthreads();

    if (warp == 0) {
        float x = (lane < 16) ? s_part[lane] : 0.0f;
#pragma unroll
        for (int off = 8; off > 0; off >>= 1)
            x += __shfl_xor_sync(0xFFFFFFFFu, x, off);
        if (lane == 0) g_batch[b] = x;
    }
}

// ---------------------------------------------------------------------------
// Kernel 3: final scalar. sum(g_batch) / (HW * B*KTOP).
// ---------------------------------------------------------------------------
__global__ void final_kernel(float* __restrict__ out)
{
    const int lane = threadIdx.x;
    float x = g_batch[lane];
#pragma unroll
    for (int off = 16; off > 0; off >>= 1)
        x += __shfl_xor_sync(0xFFFFFFFFu, x, off);
    if (lane == 0) {
        // divide by spatial count (mean) and by sum(mask) = B*KTOP
        out[0] = x / ((float)HW * (float)(B_DIM * KTOP));
    }
}

extern "C" void kernel_launch(void* const* d_in, const int* in_sizes, int n_in,
                              void* d_out, int out_size)
{
    const float* inputs  = (const float*)d_in[0];
    const float* targets = (const float*)d_in[1];
    float* out = (float*)d_out;

    bc_reduce_kernel<<<NBC, 256>>>(inputs, targets);
    select_kernel<<<B_DIM, C_DIM>>>();
    final_kernel<<<1, 32>>>(out);
}